// round 3
// baseline (speedup 1.0000x reference)
#include <cuda_runtime.h>
#include <cstddef>

// Problem constants (from reference setup_inputs): B=1, F=12, C=128, H=W=256, pad=1.
#define H_IN 256
#define W_IN 256
#define CH   128
#define H_OUT 258
#define W_OUT 258
#define PLANE_IN  (H_IN * W_IN)     // 65536
#define PLANE_OUT (H_OUT * W_OUT)   // 66564

// ---------------------------------------------------------------------------
// Interior copy: in[plane][i][j] -> out[plane][i+1][j+1]
// One thread per input float4 (aligned loads), 4 scalar stores (dest is +1
// shifted so not 16B-aligned; warp still writes contiguous 512B).
// ---------------------------------------------------------------------------
__global__ void hp_interior(const float* __restrict__ in, float* __restrict__ out) {
    int idx = blockIdx.x * blockDim.x + threadIdx.x;   // float4 index
    int plane = idx >> 14;            // 16384 float4 per plane
    int rem   = idx & 16383;
    int i     = rem >> 6;             // 64 float4 per row
    int j4    = rem & 63;

    float4 v = reinterpret_cast<const float4*>(in)[idx];
    float* o = out + (size_t)plane * PLANE_OUT + (size_t)(i + 1) * W_OUT + (j4 * 4 + 1);
    o[0] = v.x; o[1] = v.y; o[2] = v.z; o[3] = v.w;
}

// ---------------------------------------------------------------------------
// Halo fill. blockIdx.y = plane (face*CH + channel), blockIdx.x = 0..4:
//   0: top row, 1: bottom row, 2: left col, 3: right col (k = threadIdx.x in [0,256))
//   4: corners (threads 0..3: TL, TR, BL, BR)
//
// Neighbor access modes at p=1 (derived from the reference's rot90 algebra):
//   mode 0: src[k][0]     mode 1: src[0][k]
//   mode 2: src[255][k]   mode 3: src[k][255]
// ---------------------------------------------------------------------------
__global__ void hp_halo(const float* __restrict__ in, float* __restrict__ out) {
    const int plane = blockIdx.y;
    const int face  = plane >> 7;          // / CH
    const int ch    = plane & (CH - 1);
    const int grp   = face >> 2;           // 0=north, 1=equatorial, 2=south
    const int fi    = face & 3;
    const int A  = (fi + 1) & 3;
    const int B2 = (fi + 2) & 3;
    const int D  = (fi + 3) & 3;

    const size_t obase = (size_t)plane * PLANE_OUT;
    const int k = threadIdx.x;
    const int e = blockIdx.x;

    // input plane base for face g, same channel
    auto ibase = [&](int g) -> const float* {
        return in + ((size_t)g * CH + ch) * PLANE_IN;
    };

    if (e < 4) {
        int sf, mode;
        if (grp == 0) {            // northern polar faces 0-3
            switch (e) {
                case 0: sf = A;         mode = 0; break;  // top:    f[A][k,0]
                case 1: sf = 4 + fi;    mode = 1; break;  // bottom: f[4+i][0,k]
                case 2: sf = D;         mode = 1; break;  // left:   f[D][0,k]
                default:sf = 4 + A;     mode = 0; break;  // right:  f[4+A][k,0]
            }
        } else if (grp == 1) {     // equatorial faces 4-7
            switch (e) {
                case 0: sf = fi;        mode = 2; break;  // top:    f[i][255,k]
                case 1: sf = 8 + fi;    mode = 1; break;  // bottom: f[8+i][0,k]
                case 2: sf = D;         mode = 3; break;  // left:   f[D][k,255]
                default:sf = 8 + D;     mode = 0; break;  // right:  f[8+D][k,0]
            }
        } else {                   // southern polar faces 8-11
            switch (e) {
                case 0: sf = 4 + A;     mode = 2; break;  // top:    f[4+A][255,k]
                case 1: sf = 8 + D;     mode = 3; break;  // bottom: f[8+D][k,255]
                case 2: sf = 4 + fi;    mode = 3; break;  // left:   f[4+i][k,255]
                default:sf = 8 + A;     mode = 2; break;  // right:  f[8+A][255,k]
            }
        }
        const float* s = ibase(sf);
        float v;
        switch (mode) {
            case 0:  v = s[(size_t)k * W_IN];                  break;
            case 1:  v = s[k];                                 break;
            case 2:  v = s[(size_t)(H_IN - 1) * W_IN + k];     break;
            default: v = s[(size_t)k * W_IN + (W_IN - 1)];     break;
        }
        size_t dst;
        switch (e) {
            case 0:  dst = obase + (k + 1);                                   break; // row 0
            case 1:  dst = obase + (size_t)(H_OUT - 1) * W_OUT + (k + 1);     break; // row 257
            case 2:  dst = obase + (size_t)(k + 1) * W_OUT;                   break; // col 0
            default: dst = obase + (size_t)(k + 1) * W_OUT + (W_OUT - 1);     break; // col 257
        }
        out[dst] = v;
    } else if (k < 4) {
        // corners: k 0=TL(0,0) 1=TR(0,257) 2=BL(257,0) 3=BR(257,257)
        const int LAST = H_IN - 1;
        float v;
        if (grp == 0) {
            switch (k) {
                case 0:  v = ibase(B2)[0];                               break; // f[B2][0,0]
                case 1:  v = ibase(A)[0];                                break; // f[A][0,0]
                case 2:  v = ibase(D)[LAST];                             break; // f[D][0,255]
                default: v = ibase(8 + fi)[0];                           break; // f[8+i][0,0]
            }
        } else if (grp == 1) {
            switch (k) {
                case 0:  v = 0.5f * ibase(fi)[(size_t)LAST * W_IN]       // f[i][255,0]
                           + 0.5f * ibase(D)[LAST];                      break; // + f[D][0,255]
                case 1:  v = ibase(4 + A)[(size_t)LAST * W_IN];          break; // f[4+A][255,0]
                case 2:  v = ibase(4 + D)[LAST];                         break; // f[4+D][0,255]
                default: v = 0.5f * ibase(8 + fi)[LAST]                  // f[8+i][0,255]
                           + 0.5f * ibase(8 + D)[(size_t)LAST * W_IN];   break; // + f[8+D][255,0]
            }
        } else {
            const size_t LL = (size_t)LAST * W_IN + LAST;                // [255,255]
            switch (k) {
                case 0:  v = ibase(fi)[LL];     break;  // f[i][255,255]
                case 1:  v = ibase(8 + A)[LL];  break;  // f[8+A][255,255]
                case 2:  v = ibase(8 + D)[LL];  break;  // f[8+D][255,255]
                default: v = ibase(8 + B2)[LL]; break;  // f[8+B2][255,255]
            }
        }
        size_t dst;
        switch (k) {
            case 0:  dst = obase;                                               break;
            case 1:  dst = obase + (W_OUT - 1);                                 break;
            case 2:  dst = obase + (size_t)(H_OUT - 1) * W_OUT;                 break;
            default: dst = obase + (size_t)(H_OUT - 1) * W_OUT + (W_OUT - 1);   break;
        }
        out[dst] = v;
    }
}

extern "C" void kernel_launch(void* const* d_in, const int* in_sizes, int n_in,
                              void* d_out, int out_size) {
    const float* x = (const float*)d_in[0];
    float* out = (float*)d_out;

    const int n_in_elems = in_sizes[0];          // B*12*C*H*W
    const int planes = n_in_elems / PLANE_IN;    // B*12*C = 1536

    // Interior: one thread per input float4
    const int n_f4 = n_in_elems / 4;
    const int TPB = 256;
    hp_interior<<<n_f4 / TPB, TPB>>>(x, out);

    // Halo: 4 edge blocks (256 threads) + 1 corner block per plane
    dim3 grid(5, planes);
    hp_halo<<<grid, TPB>>>(x, out);

    (void)n_in; (void)out_size;
}

// round 4
// speedup vs baseline: 1.0816x; 1.0816x over previous
#include <cuda_runtime.h>
#include <cstddef>

// Problem constants: B=1, F=12, C=128, H=W=256, pad=1.
#define H_IN 256
#define W_IN 256
#define CH   128
#define H_OUT 258
#define W_OUT 258
#define PLANE_IN  (H_IN * W_IN)     // 65536
#define PLANE_OUT (H_OUT * W_OUT)   // 66564

// ---------------------------------------------------------------------------
// Fused interior copy + halo scatter.
// Each thread: one input float4 (aligned load), 4 scalar stores to the shifted
// interior position. Threads on the face boundary additionally scatter their
// edge values into the (unique) neighbor-face halo slot that consumes them.
//
// Scatter map (verified bijective against the gather table of the passing R3
// kernel; src elem (r,c) of face g -> dest halo position of face d):
//  north g:  row0   (0,c)   -> d=(g+1)&3      col0  row c+1
//            row255 (255,c) -> d=4+g          row0  col c+1
//            col0   (r,0)   -> d=(g+3)&3      row0  col r+1
//            col255 (r,255) -> d=4+((g+1)&3)  col0  row r+1
//  equat g:  row0           -> d=g            row257 col c+1
//            row255         -> d=8+((g+3)&3)  row0   col c+1
//            col0           -> d=(g+3)&3      col257 row r+1
//            col255         -> d=8+g          col0   row r+1
//  south g:  row0           -> d=4+g          row257 col c+1
//            row255         -> d=8+((g+3)&3)  col257 row c+1
//            col0           -> d=4+((g+1)&3)  col257 row r+1
//            col255         -> d=8+((g+1)&3)  row257 col r+1
// ---------------------------------------------------------------------------
__global__ void hp_main(const float* __restrict__ in, float* __restrict__ out) {
    int idx = blockIdx.x * blockDim.x + threadIdx.x;   // float4 index
    int plane = idx >> 14;            // 16384 float4 per plane
    int rem   = idx & 16383;
    int i     = rem >> 6;             // 64 float4 per row
    int j4    = rem & 63;

    float4 v = reinterpret_cast<const float4*>(in)[idx];
    {
        float* o = out + (size_t)plane * PLANE_OUT + (size_t)(i + 1) * W_OUT + (j4 * 4 + 1);
        o[0] = v.x; o[1] = v.y; o[2] = v.z; o[3] = v.w;
    }

    // Fast exit for interior threads (~97%).
    if (!((i == 0) | (i == H_IN - 1) | (j4 == 0) | (j4 == 63))) return;

    const int face = plane >> 7;
    const int ch   = plane & (CH - 1);
    const int gg   = face >> 2;       // 0=north, 1=equatorial, 2=south
    const int gi   = face & 3;
    const int j    = j4 * 4;          // src column of v.x

    auto dbase = [&](int df) -> float* {
        return out + ((size_t)df * CH + ch) * PLANE_OUT;
    };
    const size_t ROW_BOT = (size_t)(H_OUT - 1) * W_OUT;   // row 257 offset
    const int    COL_R   = W_OUT - 1;                      // col 257

    if (gg == 0) {                       // northern source faces 0-3
        if (i == 0) {                    // -> face (gi+1)&3, col0, rows j+1..j+4
            float* d = dbase((gi + 1) & 3);
            d[(size_t)(j + 1) * W_OUT] = v.x;
            d[(size_t)(j + 2) * W_OUT] = v.y;
            d[(size_t)(j + 3) * W_OUT] = v.z;
            d[(size_t)(j + 4) * W_OUT] = v.w;
        }
        if (i == H_IN - 1) {             // -> face 4+gi, row0, cols j+1..
            float* d = dbase(4 + gi);
            d[j + 1] = v.x; d[j + 2] = v.y; d[j + 3] = v.z; d[j + 4] = v.w;
        }
        if (j4 == 0)                     // (i,0) -> face (gi+3)&3, row0 col i+1
            dbase((gi + 3) & 3)[i + 1] = v.x;
        if (j4 == 63)                    // (i,255) -> face 4+((gi+1)&3), col0 row i+1
            dbase(4 + ((gi + 1) & 3))[(size_t)(i + 1) * W_OUT] = v.w;
    } else if (gg == 1) {                // equatorial source faces 4-7
        if (i == 0) {                    // -> face gi, row257, cols j+1..
            float* d = dbase(gi) + ROW_BOT;
            d[j + 1] = v.x; d[j + 2] = v.y; d[j + 3] = v.z; d[j + 4] = v.w;
        }
        if (i == H_IN - 1) {             // -> face 8+((gi+3)&3), row0, cols j+1..
            float* d = dbase(8 + ((gi + 3) & 3));
            d[j + 1] = v.x; d[j + 2] = v.y; d[j + 3] = v.z; d[j + 4] = v.w;
        }
        if (j4 == 0)                     // (i,0) -> face (gi+3)&3, col257 row i+1
            dbase((gi + 3) & 3)[(size_t)(i + 1) * W_OUT + COL_R] = v.x;
        if (j4 == 63)                    // (i,255) -> face 8+gi, col0 row i+1
            dbase(8 + gi)[(size_t)(i + 1) * W_OUT] = v.w;
    } else {                             // southern source faces 8-11
        if (i == 0) {                    // -> face 4+gi, row257, cols j+1..
            float* d = dbase(4 + gi) + ROW_BOT;
            d[j + 1] = v.x; d[j + 2] = v.y; d[j + 3] = v.z; d[j + 4] = v.w;
        }
        if (i == H_IN - 1) {             // -> face 8+((gi+3)&3), col257, rows j+1..
            float* d = dbase(8 + ((gi + 3) & 3)) + COL_R;
            d[(size_t)(j + 1) * W_OUT] = v.x;
            d[(size_t)(j + 2) * W_OUT] = v.y;
            d[(size_t)(j + 3) * W_OUT] = v.z;
            d[(size_t)(j + 4) * W_OUT] = v.w;
        }
        if (j4 == 0)                     // (i,0) -> face 4+((gi+1)&3), col257 row i+1
            dbase(4 + ((gi + 1) & 3))[(size_t)(i + 1) * W_OUT + COL_R] = v.x;
        if (j4 == 63)                    // (i,255) -> face 8+((gi+1)&3), row257 col i+1
            dbase(8 + ((gi + 1) & 3))[ROW_BOT + i + 1] = v.w;
    }
}

// ---------------------------------------------------------------------------
// Corners: one thread per plane writes its 4 corner pixels (logic identical
// to the passing R3 kernel).
// ---------------------------------------------------------------------------
__global__ void hp_corners(const float* __restrict__ in, float* __restrict__ out,
                           int planes) {
    int plane = blockIdx.x * blockDim.x + threadIdx.x;
    if (plane >= planes) return;

    const int face = plane >> 7;
    const int ch   = plane & (CH - 1);
    const int grp  = face >> 2;
    const int fi   = face & 3;
    const int A  = (fi + 1) & 3;
    const int B2 = (fi + 2) & 3;
    const int D  = (fi + 3) & 3;
    const int LAST = H_IN - 1;

    auto ibase = [&](int g) -> const float* {
        return in + ((size_t)g * CH + ch) * PLANE_IN;
    };

    float tl, tr, bl, br;
    if (grp == 0) {
        tl = ibase(B2)[0];
        tr = ibase(A)[0];
        bl = ibase(D)[LAST];
        br = ibase(8 + fi)[0];
    } else if (grp == 1) {
        tl = 0.5f * ibase(fi)[(size_t)LAST * W_IN] + 0.5f * ibase(D)[LAST];
        tr = ibase(4 + A)[(size_t)LAST * W_IN];
        bl = ibase(4 + D)[LAST];
        br = 0.5f * ibase(8 + fi)[LAST] + 0.5f * ibase(8 + D)[(size_t)LAST * W_IN];
    } else {
        const size_t LL = (size_t)LAST * W_IN + LAST;
        tl = ibase(fi)[LL];
        tr = ibase(8 + A)[LL];
        bl = ibase(8 + D)[LL];
        br = ibase(8 + B2)[LL];
    }

    float* o = out + (size_t)plane * PLANE_OUT;
    o[0]                                        = tl;
    o[W_OUT - 1]                                = tr;
    o[(size_t)(H_OUT - 1) * W_OUT]              = bl;
    o[(size_t)(H_OUT - 1) * W_OUT + W_OUT - 1]  = br;
}

extern "C" void kernel_launch(void* const* d_in, const int* in_sizes, int n_in,
                              void* d_out, int out_size) {
    const float* x = (const float*)d_in[0];
    float* out = (float*)d_out;

    const int n_in_elems = in_sizes[0];          // B*12*C*H*W
    const int planes = n_in_elems / PLANE_IN;    // 1536

    const int TPB = 256;
    const int n_f4 = n_in_elems / 4;
    hp_main<<<n_f4 / TPB, TPB>>>(x, out);
    hp_corners<<<(planes + TPB - 1) / TPB, TPB>>>(x, out, planes);

    (void)n_in; (void)out_size;
}